// round 12
// baseline (speedup 1.0000x reference)
#include <cuda_runtime.h>
#include <cstdint>

#define B_      2
#define R_      512
#define C_      256
#define C4_     64          // float4 per pixel
#define NBOX_   (B_ * R_)   // 1024
#define PROWS_  7
#define THREADS_ 256
#define MAXSPAN_ 18         // max corner x-range (spacing <= 2.65 -> span <= 18)

__global__ void __launch_bounds__(THREADS_) roialign_kernel(
    const float* __restrict__ feat0,
    const float* __restrict__ feat1,
    const float* __restrict__ rois,
    float* __restrict__ out)
{
    __shared__ __align__(128) float s_rows[2][MAXSPAN_ * C_];  // 2 x 18KB
    __shared__ __align__(16) unsigned long long s_mbar;
    __shared__ float s_w[PROWS_][4];   // folded corner weights per cell
    __shared__ int   s_x0[PROWS_], s_xp[PROWS_];
    __shared__ int   s_xmin;

    int n    = blockIdx.x;   // box
    int prow = blockIdx.y;   // pool row 0..6
    int t    = threadIdx.x;

    unsigned mbar_a = (unsigned)__cvta_generic_to_shared(&s_mbar);

    if (t == 0) {
        asm volatile("mbarrier.init.shared::cta.b64 [%0], 1;" :: "r"(mbar_a) : "memory");
        asm volatile("fence.proxy.async.shared::cta;" ::: "memory");
    }

    int lvl = 0, H = 0, y0c = 0, ypc = 0;   // thread-0 keeps these live
    if (t < PROWS_) {
        const float* roi = rois + (size_t)n * 5;
        float y1 = roi[0], x1 = roi[1], y2 = roi[2], x2 = roi[3];
        bool L = ((y2 - y1) > 48.0f) || ((x2 - x1) > 48.0f);
        lvl = L ? 1 : 0;
        H = L ? 128 : 256;
        float Hm1 = (float)(H - 1);

        const float inv = 1.0f / 1024.0f;
        float y1n = y1 * inv, x1n = x1 * inv, y2n = y2 * inv, x2n = x2 * inv;

        float ys = (y1n + ((float)prow * (1.0f / 6.0f)) * (y2n - y1n)) * Hm1;
        float xs = (x1n + ((float)t    * (1.0f / 6.0f)) * (x2n - x1n)) * Hm1;

        float vy = ((ys >= 0.0f) && (ys <= Hm1)) ? 1.0f : 0.0f;
        float vx = ((xs >= 0.0f) && (xs <= Hm1)) ? 1.0f : 0.0f;
        float v = vx * vy;

        float y0f = floorf(ys);
        float x0f = floorf(xs);
        float wy = ys - y0f;
        float wx = xs - x0f;

        y0c = (int)fminf(fmaxf(y0f, 0.0f), Hm1);
        ypc = min(y0c + 1, H - 1);
        int x0c = (int)fminf(fmaxf(x0f, 0.0f), Hm1);
        int xpc = min(x0c + 1, H - 1);

        s_x0[t] = x0c;
        s_xp[t] = xpc;

        float A  = (1.0f - wy) * v;
        float Bw = wy * v;
        s_w[t][0] = (1.0f - wx) * A;
        s_w[t][1] = wx * A;
        s_w[t][2] = (1.0f - wx) * Bw;
        s_w[t][3] = wx * Bw;
    }
    __syncthreads();

    if (t == 0) {
        int xmin = s_x0[0], xmax = s_xp[0];
        #pragma unroll
        for (int j = 1; j < PROWS_; j++) {
            xmin = min(xmin, s_x0[j]);
            xmax = max(xmax, s_xp[j]);
        }
        s_xmin = xmin;
        unsigned bytes = (unsigned)(xmax - xmin + 1) * (C_ * 4);

        const char* feat = (const char*)(lvl ? feat1 : feat0);
        int b = n >> 9;
        const char* src0 = feat + (size_t)((b * H + y0c) * H + xmin) * (C_ * 4);
        const char* src1 = feat + (size_t)((b * H + ypc) * H + xmin) * (C_ * 4);

        unsigned r0a = (unsigned)__cvta_generic_to_shared(&s_rows[0][0]);
        unsigned r1a = (unsigned)__cvta_generic_to_shared(&s_rows[1][0]);

        asm volatile("mbarrier.arrive.expect_tx.shared::cta.b64 _, [%0], %1;"
                     :: "r"(mbar_a), "r"(2u * bytes) : "memory");
        asm volatile("cp.async.bulk.shared::cluster.global.mbarrier::complete_tx::bytes "
                     "[%0], [%1], %2, [%3];"
                     :: "r"(r0a), "l"(src0), "r"(bytes), "r"(mbar_a) : "memory");
        asm volatile("cp.async.bulk.shared::cluster.global.mbarrier::complete_tx::bytes "
                     "[%0], [%1], %2, [%3];"
                     :: "r"(r1a), "l"(src1), "r"(bytes), "r"(mbar_a) : "memory");
    }
    __syncthreads();   // publish s_xmin (and s_x0/s_xp/s_w already synced)

    // wait for both bulk copies (phase 0)
    asm volatile(
        "{\n\t"
        ".reg .pred P;\n"
        "WAIT_%=: \n\t"
        "mbarrier.try_wait.parity.acquire.cta.shared::cta.b64 P, [%0], 0;\n\t"
        "@P bra DONE_%=;\n\t"
        "bra WAIT_%=;\n"
        "DONE_%=: \n\t"
        "}"
        :: "r"(mbar_a) : "memory");

    int cg  = t & (C4_ - 1);     // float4 group 0..63
    int cl0 = t >> 6;            // starting cell lane 0..3
    int xmin = s_xmin;

    const float4* r0 = (const float4*)&s_rows[0][0];
    const float4* r1 = (const float4*)&s_rows[1][0];
    float4* obase = (float4*)out + (size_t)(n * 49 + prow * PROWS_) * C4_ + cg;

    #pragma unroll
    for (int cell = cl0; cell < PROWS_; cell += 4) {
        float w00 = s_w[cell][0];
        float w01 = s_w[cell][1];
        float w10 = s_w[cell][2];
        float w11 = s_w[cell][3];
        int o0 = (s_x0[cell] - xmin) * C4_ + cg;
        int o1 = (s_xp[cell] - xmin) * C4_ + cg;

        float4 a = r0[o0];
        float4 c = r0[o1];
        float4 e = r1[o0];
        float4 f = r1[o1];

        float4 r;
        r.x = fmaf(f.x, w11, fmaf(e.x, w10, fmaf(c.x, w01, a.x * w00)));
        r.y = fmaf(f.y, w11, fmaf(e.y, w10, fmaf(c.y, w01, a.y * w00)));
        r.z = fmaf(f.z, w11, fmaf(e.z, w10, fmaf(c.z, w01, a.z * w00)));
        r.w = fmaf(f.w, w11, fmaf(e.w, w10, fmaf(c.w, w01, a.w * w00)));

        __stcs(obase + cell * C4_, r);
    }
}

extern "C" void kernel_launch(void* const* d_in, const int* in_sizes, int n_in,
                              void* d_out, int out_size)
{
    const float* feat0 = (const float*)d_in[0];
    const float* feat1 = (const float*)d_in[1];
    const float* rois  = (const float*)d_in[2];
    float* out = (float*)d_out;

    dim3 grid(NBOX_, PROWS_);
    roialign_kernel<<<grid, THREADS_>>>(feat0, feat1, rois, out);
}